// round 6
// baseline (speedup 1.0000x reference)
#include <cuda_runtime.h>
#include <math.h>

#define BB   4
#define NN   1024
#define CDIM 256
#define HH   4
#define DKK  64
#define GG   4
#define BH   (BB*HH)

// ---------------- scratch (device globals; no allocation) ----------------
__device__ float g_S   [(size_t)BH * NN * NN];   // raw cosine-relu matrix [bh][i][j]
__device__ int   g_ok  [NN];                     // diag-domination mask
__device__ int   g_allok;                        // 1 if vec == all-ones exactly
__device__ float g_vec [NN];                     // top-k union mask
__device__ float g_colw[(size_t)BB * NN];        // 0.25*sm[b,j]*vec[j]
__device__ float g_fmv [(size_t)BB * NN];        // 0.25*(sm[b,i]==0)
__device__ float g_pre [(size_t)BB * CDIM * NN]; // gconv output (stage1/2)
__device__ float g_out1[(size_t)BB * CDIM * NN]; // stage1 result (B,C,n)
__device__ float g_o1T [(size_t)BB * NN * CDIM]; // stage1 result (B,n,C)
__device__ float g_o2m [(size_t)BB * CDIM * NN]; // stage2 message

// packed dual-fp32 FMA (sm_103a; ptxas never auto-fuses — PTX only)
__device__ __forceinline__ void ffma2(unsigned long long& d,
                                      unsigned long long a, unsigned long long b) {
    asm("fma.rn.f32x2 %0, %1, %2, %0;" : "+l"(d) : "l"(a), "l"(b));
}
__device__ __forceinline__ float acc2sum(unsigned long long a) {
    float lo = __uint_as_float((unsigned int)(a & 0xffffffffu));
    float hi = __uint_as_float((unsigned int)(a >> 32));
    return lo + hi;
}

// ---------------- kernels ----------------

// Symmetric cosine GEMM (f32x2 micro), norms in-tile, zeroes okmask in block (0,0).
// Computes only lower-tri tiles (jt>=it), mirror-writes the transpose.
__global__ __launch_bounds__(256) void cos_gemm_sym_kernel(
        const float* __restrict__ X, float* __restrict__ S, int* __restrict__ okmask) {
    int bh = blockIdx.y, b = bh >> 2, h = bh & 3;
    int t = blockIdx.x;               // 0..135 tri-tile index
    if (t == 0 && bh == 0) {
        int q = threadIdx.x;
        okmask[q] = 0; okmask[q + 256] = 0; okmask[q + 512] = 0; okmask[q + 768] = 0;
    }
    int tr = (int)((sqrtf(8.0f * (float)t + 1.0f) - 1.0f) * 0.5f);
    while ((tr + 1) * (tr + 2) / 2 <= t) tr++;
    while (tr * (tr + 1) / 2 > t) tr--;
    int tc = t - tr * (tr + 1) / 2;   // tc <= tr
    int it = tc * 64, jt = tr * 64;   // jt >= it

    __shared__ float Ast[64 * 68];    // [m][k] pitch 68
    __shared__ float Bst[64 * 68];    // [n][k] pitch 68
    __shared__ float nish[64], njsh[64];
    int tid = threadIdx.x;
    const float* Ab = X + ((size_t)(b * NN + it)) * CDIM + h * DKK;
    const float* Bb = X + ((size_t)(b * NN + jt)) * CDIM + h * DKK;
    #pragma unroll
    for (int l = 0; l < 4; l++) {
        int idx = tid + l * 256;
        int m = idx >> 4, k4 = idx & 15;
        *(float4*)&Ast[m * 68 + k4 * 4] = *(const float4*)(Ab + (size_t)m * CDIM + k4 * 4);
        *(float4*)&Bst[m * 68 + k4 * 4] = *(const float4*)(Bb + (size_t)m * CDIM + k4 * 4);
    }
    __syncthreads();
    if (tid < 64) {
        float s = 0.0f;
        #pragma unroll 16
        for (int k = 0; k < DKK; k++) { float v = Ast[tid * 68 + k]; s += v * v; }
        nish[tid] = sqrtf(s);
    } else if (tid < 128) {
        int n = tid - 64;
        float s = 0.0f;
        #pragma unroll 16
        for (int k = 0; k < DKK; k++) { float v = Bst[n * 68 + k]; s += v * v; }
        njsh[n] = sqrtf(s);
    }
    int ty = tid >> 4, tx = tid & 15;
    unsigned long long acc[4][4] = {};
    #pragma unroll
    for (int k4 = 0; k4 < 16; k4++) {
        ulonglong2 a2[4], b2[4];
        #pragma unroll
        for (int u = 0; u < 4; u++) a2[u] = *(const ulonglong2*)&Ast[(ty * 4 + u) * 68 + k4 * 4];
        #pragma unroll
        for (int v = 0; v < 4; v++) b2[v] = *(const ulonglong2*)&Bst[(tx + 16 * v) * 68 + k4 * 4];
        #pragma unroll
        for (int u = 0; u < 4; u++)
            #pragma unroll
            for (int v = 0; v < 4; v++) {
                ffma2(acc[u][v], a2[u].x, b2[v].x);
                ffma2(acc[u][v], a2[u].y, b2[v].y);
            }
    }
    __syncthreads();                  // micro done everywhere; norms visible
    float ni[4], nj[4];
    #pragma unroll
    for (int u = 0; u < 4; u++) ni[u] = nish[ty * 4 + u];
    #pragma unroll
    for (int v = 0; v < 4; v++) nj[v] = njsh[tx + 16 * v];
    float* Sout = S + (size_t)bh * NN * NN;
    float sv[4][4];
    #pragma unroll
    for (int u = 0; u < 4; u++)
        #pragma unroll
        for (int v = 0; v < 4; v++) {
            float d = fmaxf(ni[u] * nj[v], 1e-8f);
            sv[u][v] = fmaxf(acc2sum(acc[u][v]) / d, 0.0f);
            Sout[(size_t)(it + ty * 4 + u) * NN + jt + tx + 16 * v] = sv[u][v];
        }
    if (it != jt) {
        float* T = Ast;               // reuse as [n][m] stage, pitch 68
        #pragma unroll
        for (int u = 0; u < 4; u++)
            #pragma unroll
            for (int v = 0; v < 4; v++)
                T[(tx + 16 * v) * 68 + ty * 4 + u] = sv[u][v];
        __syncthreads();
        #pragma unroll
        for (int l = 0; l < 4; l++) {
            int idx = tid + l * 256;
            int rr = idx >> 4, c4 = idx & 15;
            float4 o = *(const float4*)&T[rr * 68 + c4 * 4];
            *(float4*)&Sout[(size_t)(jt + rr) * NN + it + c4 * 4] = o;
        }
    }
}

// Exact check: is index i in top-4 of row (bh,i)? Counts entries that precede
// the diagonal in jax.lax.top_k order (desc value, ties -> lower index).
__global__ void diagcheck_kernel(const float* __restrict__ S, int* __restrict__ okmask) {
    int row  = blockIdx.x * 8 + (threadIdx.x >> 5);
    int lane = threadIdx.x & 31;
    int i = row & (NN - 1);
    const float* p = S + (size_t)row * NN;
    float d = p[i];
    int cnt = 0;
    #pragma unroll
    for (int l = 0; l < 8; l++) {
        int j0 = lane * 4 + l * 128;
        float4 x = *(const float4*)(p + j0);
        cnt += (x.x > d || (x.x == d && (j0 + 0) < i));
        cnt += (x.y > d || (x.y == d && (j0 + 1) < i));
        cnt += (x.z > d || (x.z == d && (j0 + 2) < i));
        cnt += (x.w > d || (x.w == d && (j0 + 3) < i));
    }
    #pragma unroll
    for (int off = 16; off; off >>= 1) cnt += __shfl_xor_sync(0xffffffffu, cnt, off);
    if (lane == 0 && cnt < 4) okmask[i] = 1;   // races: all write 1, benign
}

// vec[j] = okmask[j]; allok = AND_j okmask[j]. One block of 1024.
__global__ void vecfinal_kernel(const int* __restrict__ okmask,
                                float* __restrict__ vec, int* __restrict__ allok) {
    int j = threadIdx.x;
    int ok = okmask[j];
    vec[j] = ok ? 1.0f : 0.0f;
    int all = __syncthreads_and(ok);
    if (j == 0) *allok = all ? 1 : 0;
}

// Fallback exact top-4 union; early-exits when diag-domination proved vec==1.
__global__ void topk_kernel(const float* __restrict__ S, float* __restrict__ vec,
                            const int* __restrict__ allok) {
    if (*allok) return;
    int row  = blockIdx.x * (blockDim.x >> 5) + (threadIdx.x >> 5);
    int lane = threadIdx.x & 31;
    if (row >= BH * NN) return;
    const float* p = S + (size_t)row * NN;
    float v[4] = {-1e30f, -1e30f, -1e30f, -1e30f};
    int   id[4] = {0, 0, 0, 0};
    for (int j = lane; j < NN; j += 32) {
        float x = p[j];
        if (x > v[3]) {
            if (x > v[0])      { v[3]=v[2];id[3]=id[2]; v[2]=v[1];id[2]=id[1]; v[1]=v[0];id[1]=id[0]; v[0]=x; id[0]=j; }
            else if (x > v[1]) { v[3]=v[2];id[3]=id[2]; v[2]=v[1];id[2]=id[1]; v[1]=x; id[1]=j; }
            else if (x > v[2]) { v[3]=v[2];id[3]=id[2]; v[2]=x; id[2]=j; }
            else               { v[3]=x; id[3]=j; }
        }
    }
    #pragma unroll
    for (int r = 0; r < 4; r++) {
        float best = v[0]; int bl = lane;
        #pragma unroll
        for (int off = 16; off; off >>= 1) {
            float ov = __shfl_xor_sync(0xffffffffu, best, off);
            int   ol = __shfl_xor_sync(0xffffffffu, bl, off);
            if (ov > best || (ov == best && ol < bl)) { best = ov; bl = ol; }
        }
        int widx = __shfl_sync(0xffffffffu, id[0], bl);
        if (lane == 0) vec[widx] = 1.0f;
        if (lane == bl) { v[0]=v[1];id[0]=id[1]; v[1]=v[2];id[1]=id[2]; v[2]=v[3];id[2]=id[3]; v[3]=-1e30f; }
    }
}

// colw[b,j] = 0.25*sm[b,j]*vec[j];  fmv[b,i] = 0.25*(sm[b,i]==0)
__global__ void colprep_kernel(const int* __restrict__ smask, const float* __restrict__ vec,
                               float* __restrict__ colw, float* __restrict__ fmv) {
    int b = blockIdx.x, j = threadIdx.x;
    int s = smask[(size_t)b * NN + j];
    colw[(size_t)b * NN + j] = 0.25f * (float)s * vec[j];
    fmv [(size_t)b * NN + j] = (s == 0) ? 0.25f : 0.0f;
}

// grouped 1x1 conv + relu. Xin node-major (B,NN,CDIM); out (B,CDIM,NN).
__global__ __launch_bounds__(256) void gconv_kernel(
        const float* __restrict__ Xin, const float* __restrict__ W,
        const float* __restrict__ bias, float* __restrict__ out) {
    int b = blockIdx.z, g = blockIdx.y, nt = blockIdx.x * 64;
    __shared__ float Wst[64][65];    // [ci][o]
    __shared__ float Xst[64][65];    // [ci][n]
    int tid = threadIdx.x;
    const float* Wb = W + (size_t)g * 64 * 64;
    const float* Xb = Xin + ((size_t)b * NN + nt) * CDIM + g * 64;
    #pragma unroll
    for (int l = 0; l < 4; l++) {
        int idx = tid + l * 256; int r = idx >> 4, c4 = idx & 15;
        float4 w4 = *(const float4*)(Wb + (size_t)r * 64 + c4 * 4);
        Wst[c4*4+0][r] = w4.x; Wst[c4*4+1][r] = w4.y; Wst[c4*4+2][r] = w4.z; Wst[c4*4+3][r] = w4.w;
        float4 x4 = *(const float4*)(Xb + (size_t)r * CDIM + c4 * 4);
        Xst[c4*4+0][r] = x4.x; Xst[c4*4+1][r] = x4.y; Xst[c4*4+2][r] = x4.z; Xst[c4*4+3][r] = x4.w;
    }
    __syncthreads();
    int ty = tid >> 4, tx = tid & 15;
    float acc[4][4] = {};
    #pragma unroll 16
    for (int k = 0; k < 64; k++) {
        float a[4], bv[4];
        #pragma unroll
        for (int u = 0; u < 4; u++) a[u]  = Wst[k][ty * 4 + u];
        #pragma unroll
        for (int v = 0; v < 4; v++) bv[v] = Xst[k][tx * 4 + v];
        #pragma unroll
        for (int u = 0; u < 4; u++)
            #pragma unroll
            for (int v = 0; v < 4; v++) acc[u][v] += a[u] * bv[v];
    }
    #pragma unroll
    for (int u = 0; u < 4; u++) {
        int oc = g * 64 + ty * 4 + u;
        float bs = bias[oc];
        #pragma unroll
        for (int v = 0; v < 4; v++) {
            float val = fmaxf(acc[u][v] + bs, 0.0f);
            out[((size_t)b * CDIM + oc) * NN + nt + tx * 4 + v] = val;
        }
    }
}

// Fused message GEMM (f32x2 micro) with on-the-fly mask:
// o[b,h*64+cc,i] = sum_j U[b,h*64+cc,j] * A[bh,i,j]  (+ pre if given),
// A[bh,i,j] = S[bh,i,j]*mroi[b,i,j]*colw[b,j] + (j==i)*fmv[b,i]
__global__ __launch_bounds__(256) void ogemm_fused_kernel(
        const float* __restrict__ U, const float* __restrict__ S,
        const int* __restrict__ mroi, const float* __restrict__ colw,
        const float* __restrict__ fmv,
        const float* __restrict__ pre, float* __restrict__ out) {
    int bh = blockIdx.y, b = bh >> 2, h = bh & 3;
    int it = blockIdx.x * 64;
    __shared__ float Ust[64 * 68];   // [cc][k] pitch 68
    __shared__ float Mst[64 * 68];   // [i][k]  pitch 68 (masked A)
    const float* Ub = U  + ((size_t)b * CDIM + h * 64) * NN;
    const float* Sb = S  + ((size_t)bh * NN + it) * NN;
    const int*   Mb = mroi + ((size_t)b * NN + it) * NN;
    const float* cw = colw + (size_t)b * NN;
    const float* fv = fmv  + (size_t)b * NN + it;
    int tid = threadIdx.x, ty = tid >> 4, tx = tid & 15;
    unsigned long long acc[4][4] = {};
    for (int k0 = 0; k0 < NN; k0 += 64) {
        #pragma unroll
        for (int l = 0; l < 4; l++) {
            int idx = tid + l * 256; int r = idx >> 4, c4 = idx & 15;
            *(float4*)&Ust[r * 68 + c4 * 4] = *(const float4*)(Ub + (size_t)r * NN + k0 + c4 * 4);
            float4 s4 = *(const float4*)(Sb + (size_t)r * NN + k0 + c4 * 4);
            int4   m4 = *(const int4*)  (Mb + (size_t)r * NN + k0 + c4 * 4);
            float4 w4 = *(const float4*)(cw + k0 + c4 * 4);
            float  fm = fv[r];
            int jb = k0 + c4 * 4, ig = it + r;
            float4 o;
            o.x = s4.x * (float)m4.x * w4.x + ((jb + 0 == ig) ? fm : 0.0f);
            o.y = s4.y * (float)m4.y * w4.y + ((jb + 1 == ig) ? fm : 0.0f);
            o.z = s4.z * (float)m4.z * w4.z + ((jb + 2 == ig) ? fm : 0.0f);
            o.w = s4.w * (float)m4.w * w4.w + ((jb + 3 == ig) ? fm : 0.0f);
            *(float4*)&Mst[r * 68 + c4 * 4] = o;
        }
        __syncthreads();
        #pragma unroll
        for (int k4 = 0; k4 < 16; k4++) {
            ulonglong2 a2[4], b2[4];
            #pragma unroll
            for (int u = 0; u < 4; u++) a2[u] = *(const ulonglong2*)&Ust[(ty * 4 + u) * 68 + k4 * 4];
            #pragma unroll
            for (int v = 0; v < 4; v++) b2[v] = *(const ulonglong2*)&Mst[(tx + 16 * v) * 68 + k4 * 4];
            #pragma unroll
            for (int u = 0; u < 4; u++)
                #pragma unroll
                for (int v = 0; v < 4; v++) {
                    ffma2(acc[u][v], a2[u].x, b2[v].x);
                    ffma2(acc[u][v], a2[u].y, b2[v].y);
                }
        }
        __syncthreads();
    }
    #pragma unroll
    for (int u = 0; u < 4; u++) {
        int oc = h * 64 + ty * 4 + u;
        #pragma unroll
        for (int v = 0; v < 4; v++) {
            size_t o = ((size_t)b * CDIM + oc) * NN + it + tx + 16 * v;
            float val = acc2sum(acc[u][v]);
            if (pre != nullptr) val += pre[o];
            out[o] = val;
        }
    }
}

// (B,CDIM,NN) -> (B,NN,CDIM)
__global__ void transpose_kernel(const float* __restrict__ in, float* __restrict__ out) {
    __shared__ float t[32][33];
    int b = blockIdx.z;
    int c0 = blockIdx.y * 32, n0 = blockIdx.x * 32;
    int x = threadIdx.x, y = threadIdx.y;
    for (int yy = y; yy < 32; yy += 8)
        t[yy][x] = in[((size_t)b * CDIM + c0 + yy) * NN + n0 + x];
    __syncthreads();
    for (int yy = y; yy < 32; yy += 8)
        out[((size_t)b * NN + n0 + yy) * CDIM + c0 + x] = t[x][yy];
}

// gts[m,o] = relu(sum_c F[m,c]*W[o,c] + b[o]),  m = b*NN+n
__global__ __launch_bounds__(256) void gts_kernel(
        const float* __restrict__ F, const float* __restrict__ W,
        const float* __restrict__ bias, float* __restrict__ out) {
    int mt = blockIdx.y * 64, ntc = blockIdx.x * 64;
    __shared__ float Fst[64][65];
    __shared__ float Wst[64][65];
    int tid = threadIdx.x, ty = tid >> 4, tx = tid & 15;
    float acc[4][4] = {};
    for (int k0 = 0; k0 < CDIM; k0 += 64) {
        #pragma unroll
        for (int l = 0; l < 4; l++) {
            int idx = tid + l * 256; int r = idx >> 4, c4 = idx & 15;
            float4 f4 = *(const float4*)(F + (size_t)(mt + r) * CDIM + k0 + c4 * 4);
            Fst[c4*4+0][r] = f4.x; Fst[c4*4+1][r] = f4.y; Fst[c4*4+2][r] = f4.z; Fst[c4*4+3][r] = f4.w;
            float4 w4 = *(const float4*)(W + (size_t)(ntc + r) * CDIM + k0 + c4 * 4);
            Wst[c4*4+0][r] = w4.x; Wst[c4*4+1][r] = w4.y; Wst[c4*4+2][r] = w4.z; Wst[c4*4+3][r] = w4.w;
        }
        __syncthreads();
        #pragma unroll 16
        for (int k = 0; k < 64; k++) {
            float a[4], bv[4];
            #pragma unroll
            for (int u = 0; u < 4; u++) a[u]  = Fst[k][ty * 4 + u];
            #pragma unroll
            for (int v = 0; v < 4; v++) bv[v] = Wst[k][tx * 4 + v];
            #pragma unroll
            for (int u = 0; u < 4; u++)
                #pragma unroll
                for (int v = 0; v < 4; v++) acc[u][v] += a[u] * bv[v];
        }
        __syncthreads();
    }
    #pragma unroll
    for (int u = 0; u < 4; u++)
        #pragma unroll
        for (int v = 0; v < 4; v++) {
            int oc = ntc + tx * 4 + v;
            float val = fmaxf(acc[u][v] + bias[oc], 0.0f);
            out[(size_t)(mt + ty * 4 + u) * CDIM + oc] = val;
        }
}

// LayerNorm over channels of y[b,n,c] = o2m[b,c,n]; writes node_feat and out0.
__global__ void final_kernel(const float* __restrict__ o2m,
                             const float* __restrict__ out2pre,
                             const float* __restrict__ lnw, const float* __restrict__ lnb,
                             float* __restrict__ out0, float* __restrict__ outnf) {
    int b = blockIdx.y, n = blockIdx.x;
    int c = threadIdx.x;
    float y = o2m[((size_t)b * CDIM + c) * NN + n];
    __shared__ float s1[256], s2[256];
    s1[c] = y; s2[c] = y * y;
    __syncthreads();
    for (int st = 128; st; st >>= 1) {
        if (c < st) { s1[c] += s1[c + st]; s2[c] += s2[c + st]; }
        __syncthreads();
    }
    float mu  = s1[0] * (1.0f / CDIM);
    float var = s2[0] * (1.0f / CDIM) - mu * mu;
    float rstd = rsqrtf(fmaxf(var, 0.0f) + 1e-6f);
    float nf = (y - mu) * rstd * lnw[c] + lnb[c];
    size_t oidx = ((size_t)b * NN + n) * CDIM + c;
    outnf[oidx] = nf;
    out0[oidx]  = out2pre[((size_t)b * CDIM + c) * NN + n] + nf;
}

// ---------------- launcher ----------------
extern "C" void kernel_launch(void* const* d_in, const int* in_sizes, int n_in,
                              void* d_out, int out_size) {
    (void)in_sizes; (void)n_in; (void)out_size;
    const float* input   = (const float*)d_in[0];
    const int*   mroi    = (const int*)  d_in[1];
    const int*   smask   = (const int*)  d_in[2];
    const float* gt_feat = (const float*)d_in[3];
    const float* w1      = (const float*)d_in[4];
    const float* b1      = (const float*)d_in[5];
    const float* w2      = (const float*)d_in[6];
    const float* b2      = (const float*)d_in[7];
    const float* gt_w    = (const float*)d_in[8];
    const float* gt_b    = (const float*)d_in[9];
    const float* lnw     = (const float*)d_in[10];
    const float* lnb     = (const float*)d_in[11];

    float* out0    = (float*)d_out;                           // out2.T (B,NN,C)
    float* out_gts = out0 + (size_t)BB * NN * CDIM;           // gts
    float* out_nf  = out0 + 2 * (size_t)BB * NN * CDIM;       // node_feat

    float *S, *vec, *colw, *fmv, *pre, *out1, *o1T, *o2m;
    int *okm, *allok;
    cudaGetSymbolAddress((void**)&S,     g_S);
    cudaGetSymbolAddress((void**)&okm,   g_ok);
    cudaGetSymbolAddress((void**)&allok, g_allok);
    cudaGetSymbolAddress((void**)&vec,   g_vec);
    cudaGetSymbolAddress((void**)&colw,  g_colw);
    cudaGetSymbolAddress((void**)&fmv,   g_fmv);
    cudaGetSymbolAddress((void**)&pre,   g_pre);
    cudaGetSymbolAddress((void**)&out1,  g_out1);
    cudaGetSymbolAddress((void**)&o1T,   g_o1T);
    cudaGetSymbolAddress((void**)&o2m,   g_o2m);

    // #0 independent gts branch
    gts_kernel<<<dim3(CDIM / 64, (BB * NN) / 64), 256>>>(gt_feat, gt_w, gt_b, out_gts);
    // #1 gconv1 (independent of attention)
    gconv_kernel<<<dim3(NN / 64, GG, BB), 256>>>(input, w1, b1, pre);
    // #2 cos GEMM (zeroes okmask)
    cos_gemm_sym_kernel<<<dim3(136, BH), 256>>>(input, S, okm);
    // #3 exact diag-domination counts
    diagcheck_kernel<<<(BH * NN) / 8, 256>>>(S, okm);
    // #4 vec + allok
    vecfinal_kernel<<<1, NN>>>(okm, vec, allok);
    // #5 exact fallback (early-exits when allok)
    topk_kernel<<<(BH * NN) / 8, 256>>>(S, vec, allok);
    // #6 column/diag prep
    colprep_kernel<<<BB, NN>>>(smask, vec, colw, fmv);
    // #7 fused mask + message GEMM: out1 = pre + msg
    ogemm_fused_kernel<<<dim3(NN / 64, BH), 256>>>(pre, S, mroi, colw, fmv, pre, out1);
    // #8 transpose to node-major
    transpose_kernel<<<dim3(NN / 32, CDIM / 32, BB), dim3(32, 8)>>>(out1, o1T);

    // ---- stage 2 ----
    cos_gemm_sym_kernel<<<dim3(136, BH), 256>>>(o1T, S, okm);
    diagcheck_kernel<<<(BH * NN) / 8, 256>>>(S, okm);
    vecfinal_kernel<<<1, NN>>>(okm, vec, allok);
    topk_kernel<<<(BH * NN) / 8, 256>>>(S, vec, allok);
    colprep_kernel<<<BB, NN>>>(smask, vec, colw, fmv);
    gconv_kernel<<<dim3(NN / 64, GG, BB), 256>>>(o1T, w2, b2, pre);      // out2_pre
    ogemm_fused_kernel<<<dim3(NN / 64, BH), 256>>>(pre, S, mroi, colw, fmv, nullptr, o2m);
    final_kernel<<<dim3(NN, BB), 256>>>(o2m, pre, lnw, lnb, out0, out_nf);
}

// round 7
// speedup vs baseline: 1.2563x; 1.2563x over previous
#include <cuda_runtime.h>
#include <math.h>

#define BB   4
#define NN   1024
#define CDIM 256
#define HH   4
#define DKK  64
#define GG   4
#define BH   (BB*HH)

// ---------------- scratch (device globals; no allocation) ----------------
__device__ float g_S   [(size_t)BH * NN * NN];   // raw cosine-relu matrix [bh][i][j]
__device__ int   g_ok  [NN];                     // diag-domination mask
__device__ int   g_allok;                        // 1 if vec == all-ones exactly
__device__ float g_vec [NN];                     // top-k union mask
__device__ float g_colw[(size_t)BB * NN];        // 0.25*sm[b,j]*vec[j]
__device__ float g_fmv [(size_t)BB * NN];        // 0.25*(sm[b,i]==0)
__device__ float g_pre [(size_t)BB * CDIM * NN]; // gconv output (stage1/2)
__device__ float g_out1[(size_t)BB * CDIM * NN]; // stage1 result (B,C,n)
__device__ float g_o1T [(size_t)BB * NN * CDIM]; // stage1 result (B,n,C)
__device__ float g_o2m [(size_t)BB * CDIM * NN]; // stage2 message

// ---------------- kernels ----------------

// Symmetric cosine GEMM (R5 scalar micro), norms in-tile, zeroes okmask in one block.
// Computes only lower-tri tiles (jt>=it), mirror-writes the transpose.
__global__ __launch_bounds__(256) void cos_gemm_sym_kernel(
        const float* __restrict__ X, float* __restrict__ S, int* __restrict__ okmask) {
    int bh = blockIdx.y, b = bh >> 2, h = bh & 3;
    int t = blockIdx.x;               // 0..135 tri-tile index
    if (t == 0 && bh == 0) {
        int q = threadIdx.x;
        okmask[q] = 0; okmask[q + 256] = 0; okmask[q + 512] = 0; okmask[q + 768] = 0;
    }
    int tr = (int)((sqrtf(8.0f * (float)t + 1.0f) - 1.0f) * 0.5f);
    while ((tr + 1) * (tr + 2) / 2 <= t) tr++;
    while (tr * (tr + 1) / 2 > t) tr--;
    int tc = t - tr * (tr + 1) / 2;   // tc <= tr
    int it = tc * 64, jt = tr * 64;   // jt >= it

    __shared__ float sbuf[2 * 64 * 65];           // A | B ; reused as transpose stage
    __shared__ float nish[64], njsh[64];
    #define AST(k,m) sbuf[(k)*65 + (m)]
    #define BST(k,n) sbuf[4160 + (k)*65 + (n)]
    int tid = threadIdx.x;
    const float* Abase = X + ((size_t)(b * NN + it)) * CDIM + h * DKK;
    const float* Bbase = X + ((size_t)(b * NN + jt)) * CDIM + h * DKK;
    #pragma unroll
    for (int l = 0; l < 4; l++) {
        int idx = tid + l * 256;
        int rr = idx >> 4, c4 = idx & 15;
        float4 va = *(const float4*)(Abase + (size_t)rr * CDIM + c4 * 4);
        float4 vb = *(const float4*)(Bbase + (size_t)rr * CDIM + c4 * 4);
        AST(c4*4+0, rr) = va.x; AST(c4*4+1, rr) = va.y; AST(c4*4+2, rr) = va.z; AST(c4*4+3, rr) = va.w;
        BST(c4*4+0, rr) = vb.x; BST(c4*4+1, rr) = vb.y; BST(c4*4+2, rr) = vb.z; BST(c4*4+3, rr) = vb.w;
    }
    __syncthreads();
    // in-tile norms: threads 0..63 -> rows of A, 64..127 -> rows of B
    if (tid < 64) {
        float s = 0.0f;
        #pragma unroll 16
        for (int k = 0; k < DKK; k++) { float v = AST(k, tid); s += v * v; }
        nish[tid] = sqrtf(s);
    } else if (tid < 128) {
        int n = tid - 64;
        float s = 0.0f;
        #pragma unroll 16
        for (int k = 0; k < DKK; k++) { float v = BST(k, n); s += v * v; }
        njsh[n] = sqrtf(s);
    }
    int ty = tid >> 4, tx = tid & 15;
    float acc[4][4] = {};
    #pragma unroll 16
    for (int k = 0; k < DKK; k++) {
        float a[4], bv[4];
        #pragma unroll
        for (int u = 0; u < 4; u++) a[u]  = AST(k, ty * 4 + u);
        #pragma unroll
        for (int v = 0; v < 4; v++) bv[v] = BST(k, tx * 4 + v);
        #pragma unroll
        for (int u = 0; u < 4; u++)
            #pragma unroll
            for (int v = 0; v < 4; v++) acc[u][v] += a[u] * bv[v];
    }
    __syncthreads();                               // nish/njsh ready
    float ni[4], nj[4];
    #pragma unroll
    for (int u = 0; u < 4; u++) ni[u] = nish[ty * 4 + u];
    #pragma unroll
    for (int v = 0; v < 4; v++) nj[v] = njsh[tx * 4 + v];
    float* Sout = S + (size_t)bh * NN * NN;
    float sv[4][4];
    #pragma unroll
    for (int u = 0; u < 4; u++)
        #pragma unroll
        for (int v = 0; v < 4; v++) {
            float d = fmaxf(ni[u] * nj[v], 1e-8f);
            sv[u][v] = fmaxf(acc[u][v] / d, 0.0f);
            Sout[(size_t)(it + ty * 4 + u) * NN + jt + tx * 4 + v] = sv[u][v];
        }
    if (it != jt) {
        __syncthreads();                           // compute reads of sbuf done
        float* T = sbuf;                           // 64 x 68 stage
        #pragma unroll
        for (int u = 0; u < 4; u++)
            #pragma unroll
            for (int v = 0; v < 4; v++)
                T[(tx * 4 + v) * 68 + ty * 4 + u] = sv[u][v];
        __syncthreads();
        #pragma unroll
        for (int l = 0; l < 4; l++) {
            int idx = tid + l * 256;
            int rr = idx >> 4, c4 = idx & 15;
            float4 o = *(const float4*)&T[rr * 68 + c4 * 4];
            *(float4*)&Sout[(size_t)(jt + rr) * NN + it + c4 * 4] = o;
        }
    }
    #undef AST
    #undef BST
}

// Exact check: is index i in top-4 of row (bh,i)? Counts entries that precede
// the diagonal in jax.lax.top_k order (desc value, ties -> lower index).
__global__ void diagcheck_kernel(const float* __restrict__ S, int* __restrict__ okmask) {
    int row  = blockIdx.x * 8 + (threadIdx.x >> 5);
    int lane = threadIdx.x & 31;
    int i = row & (NN - 1);
    const float* p = S + (size_t)row * NN;
    float d = p[i];
    int cnt = 0;
    #pragma unroll
    for (int l = 0; l < 8; l++) {
        int j0 = lane * 4 + l * 128;
        float4 x = *(const float4*)(p + j0);
        cnt += (x.x > d || (x.x == d && (j0 + 0) < i));
        cnt += (x.y > d || (x.y == d && (j0 + 1) < i));
        cnt += (x.z > d || (x.z == d && (j0 + 2) < i));
        cnt += (x.w > d || (x.w == d && (j0 + 3) < i));
    }
    #pragma unroll
    for (int off = 16; off; off >>= 1) cnt += __shfl_xor_sync(0xffffffffu, cnt, off);
    if (lane == 0 && cnt < 4) okmask[i] = 1;   // races: all write 1, benign
}

// vec[j] = okmask[j]; allok = AND_j okmask[j]. One block of 1024.
__global__ void vecfinal_kernel(const int* __restrict__ okmask,
                                float* __restrict__ vec, int* __restrict__ allok) {
    int j = threadIdx.x;
    int ok = okmask[j];
    vec[j] = ok ? 1.0f : 0.0f;
    int all = __syncthreads_and(ok);
    if (j == 0) *allok = all ? 1 : 0;
}

// Fallback exact top-4 union; early-exits when diag-domination proved vec==1.
__global__ void topk_kernel(const float* __restrict__ S, float* __restrict__ vec,
                            const int* __restrict__ allok) {
    if (*allok) return;
    int row  = blockIdx.x * (blockDim.x >> 5) + (threadIdx.x >> 5);
    int lane = threadIdx.x & 31;
    if (row >= BH * NN) return;
    const float* p = S + (size_t)row * NN;
    float v[4] = {-1e30f, -1e30f, -1e30f, -1e30f};
    int   id[4] = {0, 0, 0, 0};
    for (int j = lane; j < NN; j += 32) {
        float x = p[j];
        if (x > v[3]) {
            if (x > v[0])      { v[3]=v[2];id[3]=id[2]; v[2]=v[1];id[2]=id[1]; v[1]=v[0];id[1]=id[0]; v[0]=x; id[0]=j; }
            else if (x > v[1]) { v[3]=v[2];id[3]=id[2]; v[2]=v[1];id[2]=id[1]; v[1]=x; id[1]=j; }
            else if (x > v[2]) { v[3]=v[2];id[3]=id[2]; v[2]=x; id[2]=j; }
            else               { v[3]=x; id[3]=j; }
        }
    }
    #pragma unroll
    for (int r = 0; r < 4; r++) {
        float best = v[0]; int bl = lane;
        #pragma unroll
        for (int off = 16; off; off >>= 1) {
            float ov = __shfl_xor_sync(0xffffffffu, best, off);
            int   ol = __shfl_xor_sync(0xffffffffu, bl, off);
            if (ov > best || (ov == best && ol < bl)) { best = ov; bl = ol; }
        }
        int widx = __shfl_sync(0xffffffffu, id[0], bl);
        if (lane == 0) vec[widx] = 1.0f;
        if (lane == bl) { v[0]=v[1];id[0]=id[1]; v[1]=v[2];id[1]=id[2]; v[2]=v[3];id[2]=id[3]; v[3]=-1e30f; }
    }
}

// colw[b,j] = 0.25*sm[b,j]*vec[j];  fmv[b,i] = 0.25*(sm[b,i]==0)
__global__ void colprep_kernel(const int* __restrict__ smask, const float* __restrict__ vec,
                               float* __restrict__ colw, float* __restrict__ fmv) {
    int b = blockIdx.x, j = threadIdx.x;
    int s = smask[(size_t)b * NN + j];
    colw[(size_t)b * NN + j] = 0.25f * (float)s * vec[j];
    fmv [(size_t)b * NN + j] = (s == 0) ? 0.25f : 0.0f;
}

// grouped 1x1 conv + relu. Xin node-major (B,NN,CDIM); out (B,CDIM,NN).
__global__ __launch_bounds__(256) void gconv_kernel(
        const float* __restrict__ Xin, const float* __restrict__ W,
        const float* __restrict__ bias, float* __restrict__ out) {
    int b = blockIdx.z, g = blockIdx.y, nt = blockIdx.x * 64;
    __shared__ float Wst[64][65];    // [ci][o]
    __shared__ float Xst[64][65];    // [ci][n]
    int tid = threadIdx.x;
    const float* Wb = W + (size_t)g * 64 * 64;
    const float* Xb = Xin + ((size_t)b * NN + nt) * CDIM + g * 64;
    #pragma unroll
    for (int l = 0; l < 4; l++) {
        int idx = tid + l * 256; int r = idx >> 4, c4 = idx & 15;
        float4 w4 = *(const float4*)(Wb + (size_t)r * 64 + c4 * 4);
        Wst[c4*4+0][r] = w4.x; Wst[c4*4+1][r] = w4.y; Wst[c4*4+2][r] = w4.z; Wst[c4*4+3][r] = w4.w;
        float4 x4 = *(const float4*)(Xb + (size_t)r * CDIM + c4 * 4);
        Xst[c4*4+0][r] = x4.x; Xst[c4*4+1][r] = x4.y; Xst[c4*4+2][r] = x4.z; Xst[c4*4+3][r] = x4.w;
    }
    __syncthreads();
    int ty = tid >> 4, tx = tid & 15;
    float acc[4][4] = {};
    #pragma unroll 16
    for (int k = 0; k < 64; k++) {
        float a[4], bv[4];
        #pragma unroll
        for (int u = 0; u < 4; u++) a[u]  = Wst[k][ty * 4 + u];
        #pragma unroll
        for (int v = 0; v < 4; v++) bv[v] = Xst[k][tx * 4 + v];
        #pragma unroll
        for (int u = 0; u < 4; u++)
            #pragma unroll
            for (int v = 0; v < 4; v++) acc[u][v] += a[u] * bv[v];
    }
    #pragma unroll
    for (int u = 0; u < 4; u++) {
        int oc = g * 64 + ty * 4 + u;
        float bs = bias[oc];
        #pragma unroll
        for (int v = 0; v < 4; v++) {
            float val = fmaxf(acc[u][v] + bs, 0.0f);
            out[((size_t)b * CDIM + oc) * NN + nt + tx * 4 + v] = val;
        }
    }
}

// Fused message GEMM (R5 scalar micro) with on-the-fly mask:
// o[b,h*64+cc,i] = sum_j U[b,h*64+cc,j] * A[bh,i,j]  (+ pre if given),
// A[bh,i,j] = S[bh,i,j]*mroi[b,i,j]*colw[b,j] + (j==i)*fmv[b,i]
__global__ __launch_bounds__(256) void ogemm_fused_kernel(
        const float* __restrict__ U, const float* __restrict__ S,
        const int* __restrict__ mroi, const float* __restrict__ colw,
        const float* __restrict__ fmv,
        const float* __restrict__ pre, float* __restrict__ out) {
    int bh = blockIdx.y, b = bh >> 2, h = bh & 3;
    int it = blockIdx.x * 64;
    __shared__ float Ust[64][65];    // [k][cc]
    __shared__ float Ast[64][65];    // [k][i]
    const float* Ub = U  + ((size_t)b * CDIM + h * 64) * NN;
    const float* Sb = S  + ((size_t)bh * NN + it) * NN;
    const int*   Mb = mroi + ((size_t)b * NN + it) * NN;
    const float* cw = colw + (size_t)b * NN;
    const float* fv = fmv  + (size_t)b * NN + it;
    int tid = threadIdx.x, ty = tid >> 4, tx = tid & 15;
    float acc[4][4] = {};
    for (int k0 = 0; k0 < NN; k0 += 64) {
        #pragma unroll
        for (int l = 0; l < 4; l++) {
            int idx = tid + l * 256; int r = idx >> 4, c4 = idx & 15;
            float4 u4 = *(const float4*)(Ub + (size_t)r * NN + k0 + c4 * 4);
            Ust[c4*4+0][r] = u4.x; Ust[c4*4+1][r] = u4.y; Ust[c4*4+2][r] = u4.z; Ust[c4*4+3][r] = u4.w;
            float4 s4 = *(const float4*)(Sb + (size_t)r * NN + k0 + c4 * 4);
            int4   m4 = *(const int4*)  (Mb + (size_t)r * NN + k0 + c4 * 4);
            float4 w4 = *(const float4*)(cw + k0 + c4 * 4);
            float  fm = fv[r];
            int jb = k0 + c4 * 4, ig = it + r;
            Ast[c4*4+0][r] = s4.x * (float)m4.x * w4.x + ((jb + 0 == ig) ? fm : 0.0f);
            Ast[c4*4+1][r] = s4.y * (float)m4.y * w4.y + ((jb + 1 == ig) ? fm : 0.0f);
            Ast[c4*4+2][r] = s4.z * (float)m4.z * w4.z + ((jb + 2 == ig) ? fm : 0.0f);
            Ast[c4*4+3][r] = s4.w * (float)m4.w * w4.w + ((jb + 3 == ig) ? fm : 0.0f);
        }
        __syncthreads();
        #pragma unroll 16
        for (int k = 0; k < 64; k++) {
            float a[4], bv[4];
            #pragma unroll
            for (int u = 0; u < 4; u++) a[u]  = Ust[k][ty * 4 + u];
            #pragma unroll
            for (int v = 0; v < 4; v++) bv[v] = Ast[k][tx * 4 + v];
            #pragma unroll
            for (int u = 0; u < 4; u++)
                #pragma unroll
                for (int v = 0; v < 4; v++) acc[u][v] += a[u] * bv[v];
        }
        __syncthreads();
    }
    #pragma unroll
    for (int u = 0; u < 4; u++) {
        int oc = h * 64 + ty * 4 + u;
        #pragma unroll
        for (int v = 0; v < 4; v++) {
            size_t o = ((size_t)b * CDIM + oc) * NN + it + tx * 4 + v;
            float val = acc[u][v];
            if (pre != nullptr) val += pre[o];
            out[o] = val;
        }
    }
}

// (B,CDIM,NN) -> (B,NN,CDIM)
__global__ void transpose_kernel(const float* __restrict__ in, float* __restrict__ out) {
    __shared__ float t[32][33];
    int b = blockIdx.z;
    int c0 = blockIdx.y * 32, n0 = blockIdx.x * 32;
    int x = threadIdx.x, y = threadIdx.y;
    for (int yy = y; yy < 32; yy += 8)
        t[yy][x] = in[((size_t)b * CDIM + c0 + yy) * NN + n0 + x];
    __syncthreads();
    for (int yy = y; yy < 32; yy += 8)
        out[((size_t)b * NN + n0 + yy) * CDIM + c0 + x] = t[x][yy];
}

// gts[m,o] = relu(sum_c F[m,c]*W[o,c] + b[o]),  m = b*NN+n
__global__ __launch_bounds__(256) void gts_kernel(
        const float* __restrict__ F, const float* __restrict__ W,
        const float* __restrict__ bias, float* __restrict__ out) {
    int mt = blockIdx.y * 64, ntc = blockIdx.x * 64;
    __shared__ float Fst[64][65];
    __shared__ float Wst[64][65];
    int tid = threadIdx.x, ty = tid >> 4, tx = tid & 15;
    float acc[4][4] = {};
    for (int k0 = 0; k0 < CDIM; k0 += 64) {
        #pragma unroll
        for (int l = 0; l < 4; l++) {
            int idx = tid + l * 256; int r = idx >> 4, c4 = idx & 15;
            float4 f4 = *(const float4*)(F + (size_t)(mt + r) * CDIM + k0 + c4 * 4);
            Fst[c4*4+0][r] = f4.x; Fst[c4*4+1][r] = f4.y; Fst[c4*4+2][r] = f4.z; Fst[c4*4+3][r] = f4.w;
            float4 w4 = *(const float4*)(W + (size_t)(ntc + r) * CDIM + k0 + c4 * 4);
            Wst[c4*4+0][r] = w4.x; Wst[c4*4+1][r] = w4.y; Wst[c4*4+2][r] = w4.z; Wst[c4*4+3][r] = w4.w;
        }
        __syncthreads();
        #pragma unroll 16
        for (int k = 0; k < 64; k++) {
            float a[4], bv[4];
            #pragma unroll
            for (int u = 0; u < 4; u++) a[u]  = Fst[k][ty * 4 + u];
            #pragma unroll
            for (int v = 0; v < 4; v++) bv[v] = Wst[k][tx * 4 + v];
            #pragma unroll
            for (int u = 0; u < 4; u++)
                #pragma unroll
                for (int v = 0; v < 4; v++) acc[u][v] += a[u] * bv[v];
        }
        __syncthreads();
    }
    #pragma unroll
    for (int u = 0; u < 4; u++)
        #pragma unroll
        for (int v = 0; v < 4; v++) {
            int oc = ntc + tx * 4 + v;
            float val = fmaxf(acc[u][v] + bias[oc], 0.0f);
            out[(size_t)(mt + ty * 4 + u) * CDIM + oc] = val;
        }
}

// LayerNorm over channels of y[b,n,c] = o2m[b,c,n]; writes node_feat and out0.
__global__ void final_kernel(const float* __restrict__ o2m,
                             const float* __restrict__ out2pre,
                             const float* __restrict__ lnw, const float* __restrict__ lnb,
                             float* __restrict__ out0, float* __restrict__ outnf) {
    int b = blockIdx.y, n = blockIdx.x;
    int c = threadIdx.x;
    float y = o2m[((size_t)b * CDIM + c) * NN + n];
    __shared__ float s1[256], s2[256];
    s1[c] = y; s2[c] = y * y;
    __syncthreads();
    for (int st = 128; st; st >>= 1) {
        if (c < st) { s1[c] += s1[c + st]; s2[c] += s2[c + st]; }
        __syncthreads();
    }
    float mu  = s1[0] * (1.0f / CDIM);
    float var = s2[0] * (1.0f / CDIM) - mu * mu;
    float rstd = rsqrtf(fmaxf(var, 0.0f) + 1e-6f);
    float nf = (y - mu) * rstd * lnw[c] + lnb[c];
    size_t oidx = ((size_t)b * NN + n) * CDIM + c;
    outnf[oidx] = nf;
    out0[oidx]  = out2pre[((size_t)b * CDIM + c) * NN + n] + nf;
}

// ---------------- launcher ----------------
extern "C" void kernel_launch(void* const* d_in, const int* in_sizes, int n_in,
                              void* d_out, int out_size) {
    (void)in_sizes; (void)n_in; (void)out_size;
    const float* input   = (const float*)d_in[0];
    const int*   mroi    = (const int*)  d_in[1];
    const int*   smask   = (const int*)  d_in[2];
    const float* gt_feat = (const float*)d_in[3];
    const float* w1      = (const float*)d_in[4];
    const float* b1      = (const float*)d_in[5];
    const float* w2      = (const float*)d_in[6];
    const float* b2      = (const float*)d_in[7];
    const float* gt_w    = (const float*)d_in[8];
    const float* gt_b    = (const float*)d_in[9];
    const float* lnw     = (const float*)d_in[10];
    const float* lnb     = (const float*)d_in[11];

    float* out0    = (float*)d_out;                           // out2.T (B,NN,C)
    float* out_gts = out0 + (size_t)BB * NN * CDIM;           // gts
    float* out_nf  = out0 + 2 * (size_t)BB * NN * CDIM;       // node_feat

    float *S, *vec, *colw, *fmv, *pre, *out1, *o1T, *o2m;
    int *okm, *allok;
    cudaGetSymbolAddress((void**)&S,     g_S);
    cudaGetSymbolAddress((void**)&okm,   g_ok);
    cudaGetSymbolAddress((void**)&allok, g_allok);
    cudaGetSymbolAddress((void**)&vec,   g_vec);
    cudaGetSymbolAddress((void**)&colw,  g_colw);
    cudaGetSymbolAddress((void**)&fmv,   g_fmv);
    cudaGetSymbolAddress((void**)&pre,   g_pre);
    cudaGetSymbolAddress((void**)&out1,  g_out1);
    cudaGetSymbolAddress((void**)&o1T,   g_o1T);
    cudaGetSymbolAddress((void**)&o2m,   g_o2m);

    // #0 independent gts branch
    gts_kernel<<<dim3(CDIM / 64, (BB * NN) / 64), 256>>>(gt_feat, gt_w, gt_b, out_gts);
    // #1 gconv1 (independent of attention)
    gconv_kernel<<<dim3(NN / 64, GG, BB), 256>>>(input, w1, b1, pre);
    // #2 cos GEMM (zeroes okmask)
    cos_gemm_sym_kernel<<<dim3(136, BH), 256>>>(input, S, okm);
    // #3 exact diag-domination counts
    diagcheck_kernel<<<(BH * NN) / 8, 256>>>(S, okm);
    // #4 vec + allok
    vecfinal_kernel<<<1, NN>>>(okm, vec, allok);
    // #5 exact fallback (early-exits when allok)
    topk_kernel<<<(BH * NN) / 8, 256>>>(S, vec, allok);
    // #6 column/diag prep
    colprep_kernel<<<BB, NN>>>(smask, vec, colw, fmv);
    // #7 fused mask + message GEMM: out1 = pre + msg
    ogemm_fused_kernel<<<dim3(NN / 64, BH), 256>>>(pre, S, mroi, colw, fmv, pre, out1);
    // #8 transpose to node-major
    transpose_kernel<<<dim3(NN / 32, CDIM / 32, BB), dim3(32, 8)>>>(out1, o1T);

    // ---- stage 2 ----
    cos_gemm_sym_kernel<<<dim3(136, BH), 256>>>(o1T, S, okm);
    diagcheck_kernel<<<(BH * NN) / 8, 256>>>(S, okm);
    vecfinal_kernel<<<1, NN>>>(okm, vec, allok);
    topk_kernel<<<(BH * NN) / 8, 256>>>(S, vec, allok);
    colprep_kernel<<<BB, NN>>>(smask, vec, colw, fmv);
    gconv_kernel<<<dim3(NN / 64, GG, BB), 256>>>(o1T, w2, b2, pre);      // out2_pre
    ogemm_fused_kernel<<<dim3(NN / 64, BH), 256>>>(pre, S, mroi, colw, fmv, nullptr, o2m);
    final_kernel<<<dim3(NN, BB), 256>>>(o2m, pre, lnw, lnb, out0, out_nf);
}